// round 2
// baseline (speedup 1.0000x reference)
#include <cuda_runtime.h>
#include <math.h>

#define Bdim 8192
#define Edim 4096
#define DEMB 256
#define HIDD 1024
#define DIS 128
#define SYM 512
#define DST 640   // DIS + SYM

#define BM 128
#define BN 128
#define BKt 16
#define TM 8
#define TN 8

enum { ACT_NONE = 0, ACT_RELU = 1, ACT_FSIG = 2, ACT_FINAL = 3 };

// Scratch layout (floats):
//  graph_rep : Edim*DEMB      = 1,048,576
//  state     : Bdim*DEMB      = 2,097,152
//  h1        : Bdim*HIDD      = 8,388,608
//  hm        : Bdim*HIDD      = 8,388,608
//  symtf     : Bdim*SYM       = 4,194,304
//  mu        : Bdim           =     8,192
//  symmask_f : Bdim*SYM       = 4,194,304
//  state_    : Bdim*DST       = 5,242,880
//  dlogits   : Bdim*DIS       = 1,048,576
// total = 34,611,200 floats (~138 MB)
__device__ float g_scratch[34611200];

__global__ void prep_kernel(const int* __restrict__ dialog_state,
                            const int* __restrict__ sym_mask,
                            float* __restrict__ state_,
                            float* __restrict__ symmask_f) {
    int i = blockIdx.x * blockDim.x + threadIdx.x;
    if (i < Bdim * DST) {
        int v = dialog_state[i];
        state_[i] = (v == 1) ? 1.0f : ((v == -1) ? -1.0f : 0.0f);
    }
    if (i < Bdim * SYM) {
        symmask_f[i] = (float)sym_mask[i];
    }
}

// C[M,N] = act(A[M,K] @ B[K,N] + bias), all row-major fp32.
// Requires: M % BM == 0, N % BN == 0, K % BKt == 0, N >= 128.
template <int ACT>
__global__ __launch_bounds__(256) void gemm_kernel(
    const float* __restrict__ A, const float* __restrict__ Bmat,
    const float* __restrict__ bias, float* __restrict__ C,
    int M, int N, int K,
    const float* __restrict__ mu, const float* __restrict__ symtf,
    const int* __restrict__ sflag, const int* __restrict__ smask) {
    __shared__ float As[BKt][BM + 4];
    __shared__ float Bs[BKt][BN];

    int tid = threadIdx.x;
    int bx = blockIdx.x, by = blockIdx.y;
    const float* Ab = A + (size_t)by * BM * K;
    const float* Bb = Bmat + (size_t)bx * BN;

    float acc[TM][TN];
#pragma unroll
    for (int i = 0; i < TM; i++)
#pragma unroll
        for (int j = 0; j < TN; j++) acc[i][j] = 0.0f;

    int tx = tid & 15;   // 0..15 -> N direction
    int ty = tid >> 4;   // 0..15 -> M direction

    for (int k0 = 0; k0 < K; k0 += BKt) {
        // Load A tile 128x16 (512 float4, 2 per thread), store transposed.
#pragma unroll
        for (int l = 0; l < 2; l++) {
            int idx = tid + l * 256;
            int r = idx >> 2;        // 0..127
            int c4 = idx & 3;        // 0..3
            float4 a = *(const float4*)(Ab + (size_t)r * K + k0 + c4 * 4);
            As[c4 * 4 + 0][r] = a.x;
            As[c4 * 4 + 1][r] = a.y;
            As[c4 * 4 + 2][r] = a.z;
            As[c4 * 4 + 3][r] = a.w;
        }
        // Load B tile 16x128 (512 float4, 2 per thread).
#pragma unroll
        for (int l = 0; l < 2; l++) {
            int idx = tid + l * 256;
            int r = idx >> 5;        // 0..15
            int c4 = idx & 31;       // 0..31
            *(float4*)(&Bs[r][c4 * 4]) =
                *(const float4*)(Bb + (size_t)(k0 + r) * N + c4 * 4);
        }
        __syncthreads();

#pragma unroll
        for (int k = 0; k < BKt; k++) {
            float a[TM], b[TN];
#pragma unroll
            for (int i = 0; i < TM; i++) a[i] = As[k][ty * TM + i];
#pragma unroll
            for (int j = 0; j < TN; j++) b[j] = Bs[k][tx * TN + j];
#pragma unroll
            for (int i = 0; i < TM; i++)
#pragma unroll
                for (int j = 0; j < TN; j++)
                    acc[i][j] = fmaf(a[i], b[j], acc[i][j]);
        }
        __syncthreads();
    }

#pragma unroll
    for (int i = 0; i < TM; i++) {
        int row = by * BM + ty * TM + i;
#pragma unroll
        for (int j = 0; j < TN; j++) {
            int col = bx * BN + tx * TN + j;
            float v = acc[i][j];
            if (bias) v += bias[col];
            if (ACT == ACT_RELU) {
                v = fmaxf(v, 0.0f);
            } else if (ACT == ACT_FSIG) {
                v = (v > 0.0f) ? 1.0f / (1.0f + expf(-v)) : v;
            } else if (ACT == ACT_FINAL) {
                float p = 1.0f / (1.0f + expf(-v));
                float m = mu[row];
                size_t o = (size_t)row * SYM + col;
                float tf = symtf[o];
                v = (m * p + (1.0f - m) * tf) * (float)sflag[o] * (float)smask[o];
            }
            C[(size_t)row * N + col] = v;
        }
    }
}

// One warp per row: softmax over 128 logits, multiply by disease_mask.
__global__ void softmax_mask_kernel(const float* __restrict__ logits,
                                    const int* __restrict__ dmask,
                                    float* __restrict__ out) {
    int gw = (blockIdx.x * blockDim.x + threadIdx.x) >> 5;
    int lane = threadIdx.x & 31;
    if (gw >= Bdim) return;
    const float* row = logits + (size_t)gw * DIS;
    float v0 = row[lane], v1 = row[lane + 32], v2 = row[lane + 64], v3 = row[lane + 96];
    float mx = fmaxf(fmaxf(v0, v1), fmaxf(v2, v3));
#pragma unroll
    for (int o = 16; o; o >>= 1) mx = fmaxf(mx, __shfl_xor_sync(0xffffffffu, mx, o));
    v0 = expf(v0 - mx); v1 = expf(v1 - mx); v2 = expf(v2 - mx); v3 = expf(v3 - mx);
    float s = v0 + v1 + v2 + v3;
#pragma unroll
    for (int o = 16; o; o >>= 1) s += __shfl_xor_sync(0xffffffffu, s, o);
    float inv = 1.0f / s;
    const int* dm = dmask + (size_t)gw * DIS;
    float* op = out + (size_t)gw * DIS;
    op[lane]      = v0 * inv * (float)dm[lane];
    op[lane + 32] = v1 * inv * (float)dm[lane + 32];
    op[lane + 64] = v2 * inv * (float)dm[lane + 64];
    op[lane + 96] = v3 * inv * (float)dm[lane + 96];
}

// One warp per row: mu = sigmoid(hm[row,:] . Wm2 + bm2)
__global__ void mu_kernel(const float* __restrict__ hm,
                          const float* __restrict__ Wm2,
                          const float* __restrict__ bm2,
                          float* __restrict__ mu) {
    int gw = (blockIdx.x * blockDim.x + threadIdx.x) >> 5;
    int lane = threadIdx.x & 31;
    if (gw >= Bdim) return;
    const float* row = hm + (size_t)gw * HIDD;
    float s = 0.0f;
#pragma unroll
    for (int j = 0; j < HIDD / 32; j++)
        s = fmaf(row[lane + 32 * j], Wm2[lane + 32 * j], s);
#pragma unroll
    for (int o = 16; o; o >>= 1) s += __shfl_xor_sync(0xffffffffu, s, o);
    if (lane == 0) mu[gw] = 1.0f / (1.0f + expf(-(s + bm2[0])));
}

extern "C" void kernel_launch(void* const* d_in, const int* in_sizes, int n_in,
                              void* d_out, int out_size) {
    const int*   dialog_state  = (const int*)d_in[0];
    const float* dsr           = (const float*)d_in[1];   // [B, 1, E] == [B, E]
    const float* kg_adj        = (const float*)d_in[2];
    const int*   sym_flag      = (const int*)d_in[3];
    const int*   sym_mask      = (const int*)d_in[4];
    const int*   disease_mask  = (const int*)d_in[5];
    const int*   symptoms_mask = (const int*)d_in[6];
    const float* W_g  = (const float*)d_in[7];
    const float* Wd1  = (const float*)d_in[8];
    const float* bd1  = (const float*)d_in[9];
    const float* W1   = (const float*)d_in[10];
    const float* b1   = (const float*)d_in[11];
    const float* W2   = (const float*)d_in[12];
    const float* b2   = (const float*)d_in[13];
    const float* Wm1  = (const float*)d_in[14];
    const float* bm1  = (const float*)d_in[15];
    const float* Wm2  = (const float*)d_in[16];
    const float* bm2  = (const float*)d_in[17];
    const float* m_d  = (const float*)d_in[18];

    float* out = (float*)d_out;
    float* disease_out = out;                         // [B, DIS]
    float* symptom_out = out + (size_t)Bdim * DIS;    // [B, SYM]

    float* s = nullptr;
    cudaGetSymbolAddress((void**)&s, g_scratch);
    float* graph_rep = s;
    float* state     = graph_rep + (size_t)Edim * DEMB;
    float* h1        = state + (size_t)Bdim * DEMB;
    float* hm        = h1 + (size_t)Bdim * HIDD;
    float* symtf     = hm + (size_t)Bdim * HIDD;
    float* mu        = symtf + (size_t)Bdim * SYM;
    float* symmask_f = mu + Bdim;
    float* state_    = symmask_f + (size_t)Bdim * SYM;
    float* dlogits   = state_ + (size_t)Bdim * DST;

    dim3 thr(256);

    // int -> float conversions
    prep_kernel<<<(Bdim * DST + 255) / 256, 256>>>(dialog_state, sym_mask,
                                                   state_, symmask_f);

    // graph_rep = relu(kg_adj @ W_g)           [E, DEMB]
    gemm_kernel<ACT_RELU><<<dim3(DEMB / BN, Edim / BM), thr>>>(
        kg_adj, W_g, nullptr, graph_rep, Edim, DEMB, Edim,
        nullptr, nullptr, nullptr, nullptr);

    // state = dsr @ graph_rep                  [B, DEMB]
    gemm_kernel<ACT_NONE><<<dim3(DEMB / BN, Bdim / BM), thr>>>(
        dsr, graph_rep, nullptr, state, Bdim, DEMB, Edim,
        nullptr, nullptr, nullptr, nullptr);

    // dlogits = sym_mask_f @ Wd1 + bd1         [B, DIS]
    gemm_kernel<ACT_NONE><<<dim3(DIS / BN, Bdim / BM), thr>>>(
        symmask_f, Wd1, bd1, dlogits, Bdim, DIS, SYM,
        nullptr, nullptr, nullptr, nullptr);

    // disease_dis = softmax(dlogits) * disease_mask -> d_out part 1
    softmax_mask_kernel<<<Bdim / 8, 256>>>(dlogits, disease_mask, disease_out);

    // symtf = filter_sig(disease_dis @ m_d)    [B, SYM]
    gemm_kernel<ACT_FSIG><<<dim3(SYM / BN, Bdim / BM), thr>>>(
        disease_out, m_d, nullptr, symtf, Bdim, SYM, DIS,
        nullptr, nullptr, nullptr, nullptr);

    // h1 = relu(state @ W1 + b1)               [B, HID]
    gemm_kernel<ACT_RELU><<<dim3(HIDD / BN, Bdim / BM), thr>>>(
        state, W1, b1, h1, Bdim, HIDD, DEMB,
        nullptr, nullptr, nullptr, nullptr);

    // hm = relu(state_ @ Wm1 + bm1)            [B, HID]
    gemm_kernel<ACT_RELU><<<dim3(HIDD / BN, Bdim / BM), thr>>>(
        state_, Wm1, bm1, hm, Bdim, HIDD, DST,
        nullptr, nullptr, nullptr, nullptr);

    // mu = sigmoid(hm @ Wm2 + bm2)             [B, 1]
    mu_kernel<<<Bdim / 8, 256>>>(hm, Wm2, bm2, mu);

    // symptom_final = (mu*sigmoid(h1@W2+b2) + (1-mu)*symtf) * flag * mask
    gemm_kernel<ACT_FINAL><<<dim3(SYM / BN, Bdim / BM), thr>>>(
        h1, W2, b2, symptom_out, Bdim, SYM, HIDD,
        mu, symtf, sym_flag, symptoms_mask);
}

// round 7
// speedup vs baseline: 2.2857x; 2.2857x over previous
#include <cuda_runtime.h>
#include <cuda_bf16.h>
#include <math.h>
#include <stdint.h>

#define Bdim 8192
#define Edim 4096
#define DEMB 256
#define HIDD 1024
#define DIS 128
#define SYM 512
#define DST 640   // DIS + SYM

enum { ACT_NONE = 0, ACT_RELU = 1, ACT_FSIG = 2, ACT_FINAL = 3 };
enum { OUT_F32 = 0, OUT_SPLIT = 1, OUT_SPLIT_T = 2 };

typedef __nv_bfloat16 bf16;

// ---------------- scratch layout ----------------
constexpr size_t N_KG   = (size_t)Edim * Edim;
constexpr size_t N_DSR  = (size_t)Bdim * Edim;
constexpr size_t N_ST   = (size_t)Bdim * DEMB;
constexpr size_t N_H1   = (size_t)Bdim * HIDD;
constexpr size_t N_DIS  = (size_t)Bdim * DIS;
constexpr size_t N_SYMM = (size_t)Bdim * SYM;
constexpr size_t N_STU  = (size_t)Bdim * DST;
constexpr size_t N_WG   = (size_t)Edim * DEMB;
constexpr size_t N_GR   = (size_t)Edim * DEMB;
constexpr size_t N_WD1  = (size_t)SYM * DIS;
constexpr size_t N_W1   = (size_t)DEMB * HIDD;
constexpr size_t N_W2   = (size_t)HIDD * SYM;
constexpr size_t N_WM1  = (size_t)DST * HIDD;
constexpr size_t N_MD   = (size_t)DIS * SYM;

constexpr size_t O_KG_H  = 0;
constexpr size_t O_KG_M  = O_KG_H  + N_KG;
constexpr size_t O_DSR_H = O_KG_M  + N_KG;
constexpr size_t O_DSR_M = O_DSR_H + N_DSR;
constexpr size_t O_ST_H  = O_DSR_M + N_DSR;
constexpr size_t O_ST_M  = O_ST_H  + N_ST;
constexpr size_t O_H1_H  = O_ST_M  + N_ST;
constexpr size_t O_H1_M  = O_H1_H  + N_H1;
constexpr size_t O_DIS_H = O_H1_M  + N_H1;
constexpr size_t O_DIS_M = O_DIS_H + N_DIS;
constexpr size_t O_SYMM  = O_DIS_M + N_DIS;
constexpr size_t O_STU   = O_SYMM  + N_SYMM;
constexpr size_t O_WG_H  = O_STU   + N_STU;   // W_g^T   [DEMB][E]
constexpr size_t O_WG_M  = O_WG_H  + N_WG;
constexpr size_t O_GR_H  = O_WG_M  + N_WG;    // graph_rep^T [DEMB][E]
constexpr size_t O_GR_M  = O_GR_H  + N_GR;
constexpr size_t O_WD1_H = O_GR_M  + N_GR;    // Wd1^T [DIS][SYM]
constexpr size_t O_WD1_M = O_WD1_H + N_WD1;
constexpr size_t O_W1_H  = O_WD1_M + N_WD1;   // W1^T  [HID][DEMB]
constexpr size_t O_W1_M  = O_W1_H  + N_W1;
constexpr size_t O_W2_H  = O_W1_M  + N_W1;    // W2^T  [SYM][HID]
constexpr size_t O_W2_M  = O_W2_H  + N_W2;
constexpr size_t O_WM1_H = O_W2_M  + N_W2;    // Wm1^T [HID][DST]
constexpr size_t O_WM1_M = O_WM1_H + N_WM1;
constexpr size_t O_MD_H  = O_WM1_M + N_WM1;   // m_d^T [SYM][DIS]
constexpr size_t O_MD_M  = O_MD_H  + N_MD;
constexpr size_t BF_TOTAL = O_MD_M + N_MD;

constexpr size_t F_HM    = 0;
constexpr size_t F_SYMTF = F_HM + (size_t)Bdim * HIDD;
constexpr size_t F_MU    = F_SYMTF + (size_t)Bdim * SYM;
constexpr size_t F_DLOG  = F_MU + Bdim;
constexpr size_t F_TOTAL = F_DLOG + (size_t)Bdim * DIS;

__device__ __align__(16) bf16  g_bf[BF_TOTAL];
__device__ __align__(16) float g_f32[F_TOTAL];

// ---------------- PTX helpers (sm_80-era only) ----------------
__device__ __forceinline__ uint32_t smem_u32(const void* p) {
    uint32_t a;
    asm("{ .reg .u64 t; cvta.to.shared.u64 t, %1; cvt.u32.u64 %0, t; }"
        : "=r"(a) : "l"(p));
    return a;
}
__device__ __forceinline__ void cpasync16(uint32_t dst, const void* src) {
    asm volatile("cp.async.cg.shared.global [%0], [%1], 16;" :: "r"(dst), "l"(src));
}
__device__ __forceinline__ void ldmat_x4(uint32_t* r, uint32_t addr) {
    asm volatile("ldmatrix.sync.aligned.m8n8.x4.shared.b16 {%0,%1,%2,%3}, [%4];"
                 : "=r"(r[0]), "=r"(r[1]), "=r"(r[2]), "=r"(r[3]) : "r"(addr));
}
__device__ __forceinline__ void mma16816(float* d, const uint32_t* a,
                                         uint32_t b0, uint32_t b1) {
    asm volatile("mma.sync.aligned.m16n8k16.row.col.f32.bf16.bf16.f32 "
                 "{%0,%1,%2,%3}, {%4,%5,%6,%7}, {%8,%9}, {%0,%1,%2,%3};"
                 : "+f"(d[0]), "+f"(d[1]), "+f"(d[2]), "+f"(d[3])
                 : "r"(a[0]), "r"(a[1]), "r"(a[2]), "r"(a[3]), "r"(b0), "r"(b1));
}

// ---------------- mma.sync GEMM ----------------
// C[M,N] = act(A @ B + bias); A[M][K] (hi/mid), B as BT[N][K] (hi/mid), bf16.
// BM=BN=128, BK=32. 256 thr, 8 warps (2M x 4N), warp tile 64x32.
#define TILE_B 10240            // 128 rows * 80 B (64B data + 16B pad)
#define STAGE_B (4 * TILE_B)    // Ah, Am, Bh, Bm
#define SMEM_B  (2 * STAGE_B)   // 81920

template <int AEXACT>
__device__ __forceinline__ void copy_stage(
    uint32_t base, const bf16* pa_h, const bf16* pa_m,
    const bf16* pb_h, const bf16* pb_m, int K, int k0, int tid) {
#pragma unroll
    for (int h = 0; h < 2; h++) {
        int c = tid + h * 256;          // 0..511
        int row = c >> 2, seg = c & 3;  // 128 rows x 4 segs of 16B
        uint32_t off = (uint32_t)row * 80u + (uint32_t)seg * 16u;
        size_t g = (size_t)row * K + k0 + seg * 8;
        cpasync16(base + off, pa_h + g);
        if (!AEXACT) cpasync16(base + TILE_B + off, pa_m + g);
        cpasync16(base + 2 * TILE_B + off, pb_h + g);
        cpasync16(base + 3 * TILE_B + off, pb_m + g);
    }
    asm volatile("cp.async.commit_group;" ::: "memory");
}

template <int ACT, int AEXACT, int OMODE>
__global__ __launch_bounds__(256) void mgemm(
    const bf16* __restrict__ Ah, const bf16* __restrict__ Am,
    const bf16* __restrict__ BhT, const bf16* __restrict__ BmT,
    const float* __restrict__ bias, float* __restrict__ C,
    bf16* __restrict__ Ch, bf16* __restrict__ Cm,
    int M, int N, int K,
    const float* __restrict__ mu, const float* __restrict__ symtf,
    const int* __restrict__ sflag, const int* __restrict__ smask) {
    extern __shared__ __align__(128) char smem[];
    uint32_t sb = smem_u32(smem);
    int tid = threadIdx.x, wid = tid >> 5, lane = tid & 31;
    int bx = blockIdx.x, by = blockIdx.y;
    int wm = wid & 1, wn = wid >> 1;

    const bf16* pa_h = Ah + (size_t)by * 128 * K;
    const bf16* pa_m = AEXACT ? Ah : (Am + (size_t)by * 128 * K);
    const bf16* pb_h = BhT + (size_t)bx * 128 * K;
    const bf16* pb_m = BmT + (size_t)bx * 128 * K;
    int nc = K / 32;

    float acc[4][4][4];
#pragma unroll
    for (int i = 0; i < 4; i++)
#pragma unroll
        for (int j = 0; j < 4; j++)
#pragma unroll
            for (int q = 0; q < 4; q++) acc[i][j][q] = 0.0f;

    copy_stage<AEXACT>(sb, pa_h, pa_m, pb_h, pb_m, K, 0, tid);

    for (int k = 0; k < nc; k++) {
        int st = k & 1;
        if (k + 1 < nc) {
            copy_stage<AEXACT>(sb + (st ^ 1) * STAGE_B, pa_h, pa_m, pb_h, pb_m,
                               K, (k + 1) * 32, tid);
            asm volatile("cp.async.wait_group 1;" ::: "memory");
        } else {
            asm volatile("cp.async.wait_group 0;" ::: "memory");
        }
        __syncthreads();

        uint32_t sA_h = sb + st * STAGE_B;
        uint32_t sA_m = sA_h + TILE_B;
        uint32_t sB_h = sA_h + 2 * TILE_B;
        uint32_t sB_m = sA_h + 3 * TILE_B;
#pragma unroll
        for (int kk = 0; kk < 2; kk++) {           // two k16 halves
            uint32_t kb = kk * 32;                 // byte offset in row
#pragma unroll
            for (int p = 0; p < 3; p++) {          // ah*bh, ah*bm, am*bh
                if (AEXACT && p == 2) break;
                uint32_t aB = (p == 2) ? sA_m : sA_h;
                uint32_t bB = (p == 1) ? sB_m : sB_h;
                uint32_t afr[4][4], bfr[2][4];
#pragma unroll
                for (int mt = 0; mt < 4; mt++)
                    ldmat_x4(afr[mt], aB + (uint32_t)(wm * 64 + mt * 16 + (lane & 15)) * 80
                                         + kb + (uint32_t)(lane >> 4) * 16);
#pragma unroll
                for (int pr = 0; pr < 2; pr++)
                    ldmat_x4(bfr[pr], bB + (uint32_t)(wn * 32 + pr * 16 + (lane & 15)) * 80
                                         + kb + (uint32_t)(lane >> 4) * 16);
#pragma unroll
                for (int mt = 0; mt < 4; mt++)
#pragma unroll
                    for (int nt = 0; nt < 4; nt++)
                        mma16816(acc[mt][nt], afr[mt],
                                 bfr[nt >> 1][nt & 1], bfr[nt >> 1][(nt & 1) + 2]);
            }
        }
        __syncthreads();
    }

    // ---------------- epilogue ----------------
#pragma unroll
    for (int mt = 0; mt < 4; mt++) {
#pragma unroll
        for (int nt = 0; nt < 4; nt++) {
#pragma unroll
            for (int i2 = 0; i2 < 2; i2++) {
                int row = by * 128 + wm * 64 + mt * 16 + (lane >> 2) + i2 * 8;
                int col = bx * 128 + wn * 32 + nt * 8 + (lane & 3) * 2;
                float v0 = acc[mt][nt][i2 * 2 + 0];
                float v1 = acc[mt][nt][i2 * 2 + 1];
                if (bias) { v0 += bias[col]; v1 += bias[col + 1]; }
                if (ACT == ACT_RELU) {
                    v0 = fmaxf(v0, 0.0f); v1 = fmaxf(v1, 0.0f);
                } else if (ACT == ACT_FSIG) {
                    v0 = (v0 > 0.0f) ? 1.0f / (1.0f + expf(-v0)) : v0;
                    v1 = (v1 > 0.0f) ? 1.0f / (1.0f + expf(-v1)) : v1;
                } else if (ACT == ACT_FINAL) {
                    float m = mu[row];
                    size_t o = (size_t)row * SYM + col;
                    float p0 = 1.0f / (1.0f + expf(-v0));
                    float p1 = 1.0f / (1.0f + expf(-v1));
                    v0 = (m * p0 + (1.0f - m) * symtf[o]) *
                         (float)sflag[o] * (float)smask[o];
                    v1 = (m * p1 + (1.0f - m) * symtf[o + 1]) *
                         (float)sflag[o + 1] * (float)smask[o + 1];
                }
                if (OMODE == OUT_F32) {
                    *(float2*)(C + (size_t)row * N + col) = make_float2(v0, v1);
                } else if (OMODE == OUT_SPLIT) {
                    bf16 h0 = __float2bfloat16(v0), h1 = __float2bfloat16(v1);
                    size_t o = (size_t)row * N + col;
                    *(__nv_bfloat162*)(Ch + o) = __halves2bfloat162(h0, h1);
                    *(__nv_bfloat162*)(Cm + o) = __halves2bfloat162(
                        __float2bfloat16(v0 - __bfloat162float(h0)),
                        __float2bfloat16(v1 - __bfloat162float(h1)));
                } else {  // OUT_SPLIT_T: [col][row]
                    bf16 h0 = __float2bfloat16(v0), h1 = __float2bfloat16(v1);
                    Ch[(size_t)col * M + row] = h0;
                    Ch[(size_t)(col + 1) * M + row] = h1;
                    Cm[(size_t)col * M + row] =
                        __float2bfloat16(v0 - __bfloat162float(h0));
                    Cm[(size_t)(col + 1) * M + row] =
                        __float2bfloat16(v1 - __bfloat162float(h1));
                }
            }
        }
    }
}

// ---------------- prep / split kernels ----------------
__global__ void prep_kernel(const int* __restrict__ dialog_state,
                            const int* __restrict__ sym_mask,
                            bf16* __restrict__ state_bf,
                            bf16* __restrict__ symmask_bf) {
    int i = blockIdx.x * blockDim.x + threadIdx.x;
    if (i < Bdim * DST) {
        int v = dialog_state[i];
        state_bf[i] = __float2bfloat16((v == 1) ? 1.0f : ((v == -1) ? -1.0f : 0.0f));
    }
    if (i < Bdim * SYM) symmask_bf[i] = __float2bfloat16((float)sym_mask[i]);
}

__global__ void split_a_kernel(const float* __restrict__ in,
                               bf16* __restrict__ hi, bf16* __restrict__ mid, int n4) {
    int i = blockIdx.x * blockDim.x + threadIdx.x;
    if (i >= n4) return;
    float4 v = ((const float4*)in)[i];
    bf16 h0 = __float2bfloat16(v.x), h1 = __float2bfloat16(v.y);
    bf16 h2 = __float2bfloat16(v.z), h3 = __float2bfloat16(v.w);
    bf16 m0 = __float2bfloat16(v.x - __bfloat162float(h0));
    bf16 m1 = __float2bfloat16(v.y - __bfloat162float(h1));
    bf16 m2 = __float2bfloat16(v.z - __bfloat162float(h2));
    bf16 m3 = __float2bfloat16(v.w - __bfloat162float(h3));
    ((__nv_bfloat162*)hi)[i * 2]      = __halves2bfloat162(h0, h1);
    ((__nv_bfloat162*)hi)[i * 2 + 1]  = __halves2bfloat162(h2, h3);
    ((__nv_bfloat162*)mid)[i * 2]     = __halves2bfloat162(m0, m1);
    ((__nv_bfloat162*)mid)[i * 2 + 1] = __halves2bfloat162(m2, m3);
}

// transpose + split: in [K][N] fp32 -> hiT/midT [N][K] bf16. K,N % 32 == 0.
__global__ void splitT_kernel(const float* __restrict__ in,
                              bf16* __restrict__ hiT, bf16* __restrict__ midT,
                              int K, int N) {
    __shared__ float t[32][33];
    int tx = threadIdx.x, ty = threadIdx.y;
    int n0 = blockIdx.x * 32, k0 = blockIdx.y * 32;
#pragma unroll
    for (int j = ty; j < 32; j += 8)
        t[j][tx] = in[(size_t)(k0 + j) * N + n0 + tx];
    __syncthreads();
#pragma unroll
    for (int j = ty; j < 32; j += 8) {
        float v = t[tx][j];
        bf16 h = __float2bfloat16(v);
        size_t o = (size_t)(n0 + j) * K + k0 + tx;
        hiT[o] = h;
        midT[o] = __float2bfloat16(v - __bfloat162float(h));
    }
}

__global__ void softmax_mask_kernel(const float* __restrict__ logits,
                                    const int* __restrict__ dmask,
                                    float* __restrict__ out,
                                    bf16* __restrict__ oh, bf16* __restrict__ om) {
    int gw = (blockIdx.x * blockDim.x + threadIdx.x) >> 5;
    int lane = threadIdx.x & 31;
    if (gw >= Bdim) return;
    const float* row = logits + (size_t)gw * DIS;
    float v0 = row[lane], v1 = row[lane + 32], v2 = row[lane + 64], v3 = row[lane + 96];
    float mx = fmaxf(fmaxf(v0, v1), fmaxf(v2, v3));
#pragma unroll
    for (int o = 16; o; o >>= 1) mx = fmaxf(mx, __shfl_xor_sync(0xffffffffu, mx, o));
    v0 = expf(v0 - mx); v1 = expf(v1 - mx); v2 = expf(v2 - mx); v3 = expf(v3 - mx);
    float s = v0 + v1 + v2 + v3;
#pragma unroll
    for (int o = 16; o; o >>= 1) s += __shfl_xor_sync(0xffffffffu, s, o);
    float inv = 1.0f / s;
    const int* dm = dmask + (size_t)gw * DIS;
    size_t base = (size_t)gw * DIS;
#pragma unroll
    for (int q = 0; q < 4; q++) {
        float v = (q == 0 ? v0 : q == 1 ? v1 : q == 2 ? v2 : v3) * inv *
                  (float)dm[lane + q * 32];
        size_t o = base + lane + q * 32;
        out[o] = v;
        bf16 h = __float2bfloat16(v);
        oh[o] = h;
        om[o] = __float2bfloat16(v - __bfloat162float(h));
    }
}

__global__ void mu_kernel(const float* __restrict__ hm,
                          const float* __restrict__ Wm2,
                          const float* __restrict__ bm2,
                          float* __restrict__ mu) {
    int gw = (blockIdx.x * blockDim.x + threadIdx.x) >> 5;
    int lane = threadIdx.x & 31;
    if (gw >= Bdim) return;
    const float* row = hm + (size_t)gw * HIDD;
    float s = 0.0f;
#pragma unroll
    for (int j = 0; j < HIDD / 32; j++)
        s = fmaf(row[lane + 32 * j], Wm2[lane + 32 * j], s);
#pragma unroll
    for (int o = 16; o; o >>= 1) s += __shfl_xor_sync(0xffffffffu, s, o);
    if (lane == 0) mu[gw] = 1.0f / (1.0f + expf(-(s + bm2[0])));
}

// ---------------- launch ----------------
extern "C" void kernel_launch(void* const* d_in, const int* in_sizes, int n_in,
                              void* d_out, int out_size) {
    const int*   dialog_state  = (const int*)d_in[0];
    const float* dsr           = (const float*)d_in[1];
    const float* kg_adj        = (const float*)d_in[2];
    const int*   sym_flag      = (const int*)d_in[3];
    const int*   sym_mask      = (const int*)d_in[4];
    const int*   disease_mask  = (const int*)d_in[5];
    const int*   symptoms_mask = (const int*)d_in[6];
    const float* W_g  = (const float*)d_in[7];
    const float* Wd1  = (const float*)d_in[8];
    const float* bd1  = (const float*)d_in[9];
    const float* W1   = (const float*)d_in[10];
    const float* b1   = (const float*)d_in[11];
    const float* W2   = (const float*)d_in[12];
    const float* b2   = (const float*)d_in[13];
    const float* Wm1  = (const float*)d_in[14];
    const float* bm1  = (const float*)d_in[15];
    const float* Wm2  = (const float*)d_in[16];
    const float* bm2  = (const float*)d_in[17];
    const float* m_d  = (const float*)d_in[18];

    float* out = (float*)d_out;
    float* disease_out = out;
    float* symptom_out = out + (size_t)Bdim * DIS;

    bf16* bp = nullptr;  float* fp = nullptr;
    cudaGetSymbolAddress((void**)&bp, g_bf);
    cudaGetSymbolAddress((void**)&fp, g_f32);

    float* hm      = fp + F_HM;
    float* symtf   = fp + F_SYMTF;
    float* mu      = fp + F_MU;
    float* dlogits = fp + F_DLOG;

    cudaFuncSetAttribute(mgemm<ACT_RELU, 0, OUT_SPLIT_T>, cudaFuncAttributeMaxDynamicSharedMemorySize, SMEM_B);
    cudaFuncSetAttribute(mgemm<ACT_NONE, 0, OUT_SPLIT>,   cudaFuncAttributeMaxDynamicSharedMemorySize, SMEM_B);
    cudaFuncSetAttribute(mgemm<ACT_NONE, 1, OUT_F32>,     cudaFuncAttributeMaxDynamicSharedMemorySize, SMEM_B);
    cudaFuncSetAttribute(mgemm<ACT_FSIG, 0, OUT_F32>,     cudaFuncAttributeMaxDynamicSharedMemorySize, SMEM_B);
    cudaFuncSetAttribute(mgemm<ACT_RELU, 0, OUT_SPLIT>,   cudaFuncAttributeMaxDynamicSharedMemorySize, SMEM_B);
    cudaFuncSetAttribute(mgemm<ACT_RELU, 1, OUT_F32>,     cudaFuncAttributeMaxDynamicSharedMemorySize, SMEM_B);
    cudaFuncSetAttribute(mgemm<ACT_FINAL, 0, OUT_F32>,    cudaFuncAttributeMaxDynamicSharedMemorySize, SMEM_B);

    prep_kernel<<<(Bdim * DST + 255) / 256, 256>>>(dialog_state, sym_mask,
                                                   bp + O_STU, bp + O_SYMM);
    split_a_kernel<<<(int)((N_KG / 4 + 255) / 256), 256>>>(
        kg_adj, bp + O_KG_H, bp + O_KG_M, (int)(N_KG / 4));
    split_a_kernel<<<(int)((N_DSR / 4 + 255) / 256), 256>>>(
        dsr, bp + O_DSR_H, bp + O_DSR_M, (int)(N_DSR / 4));
    dim3 tb(32, 8);
    splitT_kernel<<<dim3(DEMB / 32, Edim / 32), tb>>>(W_g, bp + O_WG_H, bp + O_WG_M, Edim, DEMB);
    splitT_kernel<<<dim3(DIS / 32, SYM / 32), tb>>>(Wd1, bp + O_WD1_H, bp + O_WD1_M, SYM, DIS);
    splitT_kernel<<<dim3(HIDD / 32, DEMB / 32), tb>>>(W1, bp + O_W1_H, bp + O_W1_M, DEMB, HIDD);
    splitT_kernel<<<dim3(SYM / 32, HIDD / 32), tb>>>(W2, bp + O_W2_H, bp + O_W2_M, HIDD, SYM);
    splitT_kernel<<<dim3(HIDD / 32, DST / 32), tb>>>(Wm1, bp + O_WM1_H, bp + O_WM1_M, DST, HIDD);
    splitT_kernel<<<dim3(SYM / 32, DIS / 32), tb>>>(m_d, bp + O_MD_H, bp + O_MD_M, DIS, SYM);

    // G1: graph_rep^T = relu(kg_adj @ W_g)^T -> split T   [DEMB][E]
    mgemm<ACT_RELU, 0, OUT_SPLIT_T><<<dim3(DEMB / 128, Edim / 128), 256, SMEM_B>>>(
        bp + O_KG_H, bp + O_KG_M, bp + O_WG_H, bp + O_WG_M,
        nullptr, nullptr, bp + O_GR_H, bp + O_GR_M,
        Edim, DEMB, Edim, nullptr, nullptr, nullptr, nullptr);

    // G2: state = dsr @ graph_rep -> split   [B][DEMB], K=E
    mgemm<ACT_NONE, 0, OUT_SPLIT><<<dim3(DEMB / 128, Bdim / 128), 256, SMEM_B>>>(
        bp + O_DSR_H, bp + O_DSR_M, bp + O_GR_H, bp + O_GR_M,
        nullptr, nullptr, bp + O_ST_H, bp + O_ST_M,
        Bdim, DEMB, Edim, nullptr, nullptr, nullptr, nullptr);

    // G3: dlogits = sym_mask @ Wd1 + bd1 (A exact)  [B][DIS], K=SYM
    mgemm<ACT_NONE, 1, OUT_F32><<<dim3(DIS / 128, Bdim / 128), 256, SMEM_B>>>(
        bp + O_SYMM, nullptr, bp + O_WD1_H, bp + O_WD1_M,
        bd1, dlogits, nullptr, nullptr,
        Bdim, DIS, SYM, nullptr, nullptr, nullptr, nullptr);

    softmax_mask_kernel<<<Bdim / 8, 256>>>(dlogits, disease_mask, disease_out,
                                           bp + O_DIS_H, bp + O_DIS_M);

    // G4: symtf = filter_sig(disease @ m_d)  [B][SYM], K=DIS
    mgemm<ACT_FSIG, 0, OUT_F32><<<dim3(SYM / 128, Bdim / 128), 256, SMEM_B>>>(
        bp + O_DIS_H, bp + O_DIS_M, bp + O_MD_H, bp + O_MD_M,
        nullptr, symtf, nullptr, nullptr,
        Bdim, SYM, DIS, nullptr, nullptr, nullptr, nullptr);

    // G5: h1 = relu(state @ W1 + b1) -> split  [B][HID], K=DEMB
    mgemm<ACT_RELU, 0, OUT_SPLIT><<<dim3(HIDD / 128, Bdim / 128), 256, SMEM_B>>>(
        bp + O_ST_H, bp + O_ST_M, bp + O_W1_H, bp + O_W1_M,
        b1, nullptr, bp + O_H1_H, bp + O_H1_M,
        Bdim, HIDD, DEMB, nullptr, nullptr, nullptr, nullptr);

    // G6: hm = relu(state_ @ Wm1 + bm1) (A exact)  [B][HID], K=DST
    mgemm<ACT_RELU, 1, OUT_F32><<<dim3(HIDD / 128, Bdim / 128), 256, SMEM_B>>>(
        bp + O_STU, nullptr, bp + O_WM1_H, bp + O_WM1_M,
        bm1, hm, nullptr, nullptr,
        Bdim, HIDD, DST, nullptr, nullptr, nullptr, nullptr);

    mu_kernel<<<Bdim / 8, 256>>>(hm, Wm2, bm2, mu);

    // G7: symptom_final  [B][SYM], K=HID
    mgemm<ACT_FINAL, 0, OUT_F32><<<dim3(SYM / 128, Bdim / 128), 256, SMEM_B>>>(
        bp + O_H1_H, bp + O_H1_M, bp + O_W2_H, bp + O_W2_M,
        b2, symptom_out, nullptr, nullptr,
        Bdim, SYM, HIDD, mu, symtf, sym_flag, symptoms_mask);
}

// round 8
// speedup vs baseline: 2.7726x; 1.2130x over previous
#include <cuda_runtime.h>
#include <cuda_bf16.h>
#include <math.h>
#include <stdint.h>

#define Bdim 8192
#define Edim 4096
#define DEMB 256
#define HIDD 1024
#define DIS 128
#define SYM 512
#define DST 640   // DIS + SYM

enum { ACT_NONE = 0, ACT_RELU = 1, ACT_FSIG = 2, ACT_FINAL = 3 };
enum { OUT_F32 = 0, OUT_SPLIT = 1, OUT_SPLIT_T = 2 };
enum { A_PRE = 0, A_EXACT = 1, A_F32 = 2 };

typedef __nv_bfloat16 bf16;

// ---------------- scratch layout ----------------
constexpr size_t N_ST   = (size_t)Bdim * DEMB;
constexpr size_t N_H1   = (size_t)Bdim * HIDD;
constexpr size_t N_DIS  = (size_t)Bdim * DIS;
constexpr size_t N_SYMM = (size_t)Bdim * SYM;
constexpr size_t N_STU  = (size_t)Bdim * DST;
constexpr size_t N_WG   = (size_t)Edim * DEMB;
constexpr size_t N_GR   = (size_t)Edim * DEMB;
constexpr size_t N_WD1  = (size_t)SYM * DIS;
constexpr size_t N_W1   = (size_t)DEMB * HIDD;
constexpr size_t N_W2   = (size_t)HIDD * SYM;
constexpr size_t N_WM1  = (size_t)DST * HIDD;
constexpr size_t N_MD   = (size_t)DIS * SYM;

constexpr size_t O_ST_H  = 0;
constexpr size_t O_ST_M  = O_ST_H  + N_ST;
constexpr size_t O_H1_H  = O_ST_M  + N_ST;
constexpr size_t O_H1_M  = O_H1_H  + N_H1;
constexpr size_t O_DIS_H = O_H1_M  + N_H1;
constexpr size_t O_DIS_M = O_DIS_H + N_DIS;
constexpr size_t O_SYMM  = O_DIS_M + N_DIS;
constexpr size_t O_STU   = O_SYMM  + N_SYMM;
constexpr size_t O_WG_H  = O_STU   + N_STU;   // W_g^T   [DEMB][E]
constexpr size_t O_WG_M  = O_WG_H  + N_WG;
constexpr size_t O_GR_H  = O_WG_M  + N_WG;    // graph_rep^T [DEMB][E]
constexpr size_t O_GR_M  = O_GR_H  + N_GR;
constexpr size_t O_WD1_H = O_GR_M  + N_GR;    // Wd1^T [DIS][SYM]
constexpr size_t O_WD1_M = O_WD1_H + N_WD1;
constexpr size_t O_W1_H  = O_WD1_M + N_WD1;   // W1^T  [HID][DEMB]
constexpr size_t O_W1_M  = O_W1_H  + N_W1;
constexpr size_t O_W2_H  = O_W1_M  + N_W1;    // W2^T  [SYM][HID]
constexpr size_t O_W2_M  = O_W2_H  + N_W2;
constexpr size_t O_WM1_H = O_W2_M  + N_W2;    // Wm1^T [HID][DST]
constexpr size_t O_WM1_M = O_WM1_H + N_WM1;
constexpr size_t O_MD_H  = O_WM1_M + N_WM1;   // m_d^T [SYM][DIS]
constexpr size_t O_MD_M  = O_MD_H  + N_MD;
constexpr size_t BF_TOTAL = O_MD_M + N_MD;

constexpr size_t F_HM    = 0;
constexpr size_t F_SYMTF = F_HM + (size_t)Bdim * HIDD;
constexpr size_t F_MU    = F_SYMTF + (size_t)Bdim * SYM;
constexpr size_t F_DLOG  = F_MU + Bdim;
constexpr size_t F_TOTAL = F_DLOG + (size_t)Bdim * DIS;

__device__ __align__(16) bf16  g_bf[BF_TOTAL];
__device__ __align__(16) float g_f32[F_TOTAL];

// ---------------- PTX helpers (sm_80-era only) ----------------
__device__ __forceinline__ uint32_t smem_u32(const void* p) {
    uint32_t a;
    asm("{ .reg .u64 t; cvta.to.shared.u64 t, %1; cvt.u32.u64 %0, t; }"
        : "=r"(a) : "l"(p));
    return a;
}
__device__ __forceinline__ void cpasync16(uint32_t dst, const void* src) {
    asm volatile("cp.async.cg.shared.global [%0], [%1], 16;" :: "r"(dst), "l"(src));
}
__device__ __forceinline__ void ldmat_x4(uint32_t* r, uint32_t addr) {
    asm volatile("ldmatrix.sync.aligned.m8n8.x4.shared.b16 {%0,%1,%2,%3}, [%4];"
                 : "=r"(r[0]), "=r"(r[1]), "=r"(r[2]), "=r"(r[3]) : "r"(addr));
}
__device__ __forceinline__ void mma16816(float* d, const uint32_t* a,
                                         uint32_t b0, uint32_t b1) {
    asm volatile("mma.sync.aligned.m16n8k16.row.col.f32.bf16.bf16.f32 "
                 "{%0,%1,%2,%3}, {%4,%5,%6,%7}, {%8,%9}, {%0,%1,%2,%3};"
                 : "+f"(d[0]), "+f"(d[1]), "+f"(d[2]), "+f"(d[3])
                 : "r"(a[0]), "r"(a[1]), "r"(a[2]), "r"(a[3]), "r"(b0), "r"(b1));
}

// ---------------- mma.sync GEMM ----------------
// C[M,N] = act(A @ B + bias); A[M][K], B as BT[N][K], bf16 hi/mid split.
// BM = 32*MT, BN = 128. BK=32. 256 thr, 8 warps (2M x 4N), warp tile (16*MT)x32.
#define BTILE_B 10240           // 128 rows * 80 B (64B data + 16B pad)

template <int ACT, int AMODE, int OMODE, int MT>
__global__ __launch_bounds__(256) void mgemm(
    const bf16* __restrict__ Ah, const bf16* __restrict__ Am,
    const float* __restrict__ Af,
    const bf16* __restrict__ BhT, const bf16* __restrict__ BmT,
    const float* __restrict__ bias, float* __restrict__ C,
    bf16* __restrict__ Ch, bf16* __restrict__ Cm,
    int M, int N, int K,
    const float* __restrict__ mu, const float* __restrict__ symtf,
    const int* __restrict__ sflag, const int* __restrict__ smask) {
    constexpr int BM = 32 * MT;
    constexpr int A_T = BM * 80;            // bytes per A half-tile in smem
    constexpr int STAGE = 2 * A_T + 2 * BTILE_B;
    constexpr int NV = BM / 32;             // float4 per thread for A_F32
    constexpr int AI = (BM * 4 + 255) / 256;// cp.async iters for A

    extern __shared__ __align__(128) char smem[];
    uint32_t sb = smem_u32(smem);
    int tid = threadIdx.x, wid = tid >> 5, lane = tid & 31;
    int bx = blockIdx.x, by = blockIdx.y;
    int wm = wid & 1, wn = wid >> 1;

    const bf16* pa_h = (AMODE == A_F32) ? nullptr : Ah + (size_t)by * BM * K;
    const bf16* pa_m = (AMODE == A_PRE) ? Am + (size_t)by * BM * K : pa_h;
    const float* paf = (AMODE == A_F32) ? Af + (size_t)by * BM * K : nullptr;
    const bf16* pb_h = BhT + (size_t)bx * 128 * K;
    const bf16* pb_m = BmT + (size_t)bx * 128 * K;
    int nc = K / 32;

    float acc[MT][4][4];
#pragma unroll
    for (int i = 0; i < MT; i++)
#pragma unroll
        for (int j = 0; j < 4; j++)
#pragma unroll
            for (int q = 0; q < 4; q++) acc[i][j][q] = 0.0f;

    // ---- helpers as lambdas ----
    auto copyB = [&](uint32_t base, int k0) {
#pragma unroll
        for (int h = 0; h < 2; h++) {
            int c = tid + h * 256;
            int row = c >> 2, seg = c & 3;
            uint32_t off = (uint32_t)row * 80u + (uint32_t)seg * 16u;
            size_t g = (size_t)row * K + k0 + seg * 8;
            cpasync16(base + 2 * A_T + off, pb_h + g);
            cpasync16(base + 2 * A_T + BTILE_B + off, pb_m + g);
        }
    };
    auto copyA_pre = [&](uint32_t base, int k0) {
#pragma unroll
        for (int h = 0; h < AI; h++) {
            int c = tid + h * 256;
            if (BM * 4 % 256 != 0 && c >= BM * 4) break;
            int row = c >> 2, seg = c & 3;
            uint32_t off = (uint32_t)row * 80u + (uint32_t)seg * 16u;
            size_t g = (size_t)row * K + k0 + seg * 8;
            cpasync16(base + off, pa_h + g);
            if (AMODE == A_PRE) cpasync16(base + A_T + off, pa_m + g);
        }
    };
    auto stsA_f32 = [&](char* cbase, const float4* v) {
#pragma unroll
        for (int i = 0; i < NV; i++) {
            int idx = tid + i * 256;
            int row = idx >> 3, c4 = idx & 7;
            char* d = cbase + row * 80 + c4 * 8;
            bf16 h0 = __float2bfloat16(v[i].x), h1 = __float2bfloat16(v[i].y);
            bf16 h2 = __float2bfloat16(v[i].z), h3 = __float2bfloat16(v[i].w);
            *(__nv_bfloat162*)(d)     = __halves2bfloat162(h0, h1);
            *(__nv_bfloat162*)(d + 4) = __halves2bfloat162(h2, h3);
            char* dm = d + A_T;
            *(__nv_bfloat162*)(dm)     = __halves2bfloat162(
                __float2bfloat16(v[i].x - __bfloat162float(h0)),
                __float2bfloat16(v[i].y - __bfloat162float(h1)));
            *(__nv_bfloat162*)(dm + 4) = __halves2bfloat162(
                __float2bfloat16(v[i].z - __bfloat162float(h2)),
                __float2bfloat16(v[i].w - __bfloat162float(h3)));
        }
    };
    auto ldgA_f32 = [&](float4* v, int k0) {
#pragma unroll
        for (int i = 0; i < NV; i++) {
            int idx = tid + i * 256;
            int row = idx >> 3, c4 = idx & 7;
            v[i] = *(const float4*)(paf + (size_t)row * K + k0 + c4 * 4);
        }
    };

    // ---- prologue: stage 0 ----
    if (AMODE == A_F32) {
        float4 v0[NV];
        ldgA_f32(v0, 0);
        stsA_f32(smem, v0);
    } else {
        copyA_pre(sb, 0);
    }
    copyB(sb, 0);
    asm volatile("cp.async.commit_group;" ::: "memory");
    asm volatile("cp.async.wait_group 0;" ::: "memory");
    __syncthreads();

    // ---- main loop ----
    for (int k = 0; k < nc; k++) {
        int st = k & 1;
        uint32_t sbase = sb + st * STAGE;
        char* cbase_n = smem + (st ^ 1) * STAGE;
        uint32_t sbase_n = sb + (st ^ 1) * STAGE;

        float4 afv[NV];
        bool more = (k + 1 < nc);
        if (more) {
            if (AMODE == A_F32) ldgA_f32(afv, (k + 1) * 32);
            else copyA_pre(sbase_n, (k + 1) * 32);
            copyB(sbase_n, (k + 1) * 32);
            asm volatile("cp.async.commit_group;" ::: "memory");
        }

        uint32_t sA_h = sbase;
        uint32_t sA_m = sbase + A_T;
        uint32_t sB_h = sbase + 2 * A_T;
        uint32_t sB_m = sbase + 2 * A_T + BTILE_B;
#pragma unroll
        for (int kk = 0; kk < 2; kk++) {
            uint32_t kb = kk * 32;
#pragma unroll
            for (int p = 0; p < 3; p++) {           // ah*bh, ah*bm, am*bh
                if (AMODE == A_EXACT && p == 2) break;
                uint32_t aB = (p == 2) ? sA_m : sA_h;
                uint32_t bB = (p == 1) ? sB_m : sB_h;
                uint32_t afr[MT][4], bfr[2][4];
#pragma unroll
                for (int mt = 0; mt < MT; mt++)
                    ldmat_x4(afr[mt], aB + (uint32_t)(wm * (16 * MT) + mt * 16 + (lane & 15)) * 80
                                         + kb + (uint32_t)(lane >> 4) * 16);
#pragma unroll
                for (int pr = 0; pr < 2; pr++)
                    ldmat_x4(bfr[pr], bB + (uint32_t)(wn * 32 + pr * 16 + (lane & 15)) * 80
                                         + kb + (uint32_t)(lane >> 4) * 16);
#pragma unroll
                for (int mt = 0; mt < MT; mt++)
#pragma unroll
                    for (int nt = 0; nt < 4; nt++)
                        mma16816(acc[mt][nt], afr[mt],
                                 bfr[nt >> 1][nt & 1], bfr[nt >> 1][(nt & 1) + 2]);
            }
        }

        if (more) {
            if (AMODE == A_F32) stsA_f32(cbase_n, afv);
            asm volatile("cp.async.wait_group 0;" ::: "memory");
        }
        __syncthreads();
    }

    // ---------------- epilogue ----------------
#pragma unroll
    for (int mt = 0; mt < MT; mt++) {
#pragma unroll
        for (int nt = 0; nt < 4; nt++) {
#pragma unroll
            for (int i2 = 0; i2 < 2; i2++) {
                int row = by * BM + wm * (16 * MT) + mt * 16 + (lane >> 2) + i2 * 8;
                int col = bx * 128 + wn * 32 + nt * 8 + (lane & 3) * 2;
                float v0 = acc[mt][nt][i2 * 2 + 0];
                float v1 = acc[mt][nt][i2 * 2 + 1];
                if (bias) { v0 += bias[col]; v1 += bias[col + 1]; }
                if (ACT == ACT_RELU) {
                    v0 = fmaxf(v0, 0.0f); v1 = fmaxf(v1, 0.0f);
                } else if (ACT == ACT_FSIG) {
                    v0 = (v0 > 0.0f) ? 1.0f / (1.0f + expf(-v0)) : v0;
                    v1 = (v1 > 0.0f) ? 1.0f / (1.0f + expf(-v1)) : v1;
                } else if (ACT == ACT_FINAL) {
                    float m = mu[row];
                    size_t o = (size_t)row * SYM + col;
                    float p0 = 1.0f / (1.0f + expf(-v0));
                    float p1 = 1.0f / (1.0f + expf(-v1));
                    v0 = (m * p0 + (1.0f - m) * symtf[o]) *
                         (float)sflag[o] * (float)smask[o];
                    v1 = (m * p1 + (1.0f - m) * symtf[o + 1]) *
                         (float)sflag[o + 1] * (float)smask[o + 1];
                }
                if (OMODE == OUT_F32) {
                    *(float2*)(C + (size_t)row * N + col) = make_float2(v0, v1);
                } else if (OMODE == OUT_SPLIT) {
                    bf16 h0 = __float2bfloat16(v0), h1 = __float2bfloat16(v1);
                    size_t o = (size_t)row * N + col;
                    *(__nv_bfloat162*)(Ch + o) = __halves2bfloat162(h0, h1);
                    *(__nv_bfloat162*)(Cm + o) = __halves2bfloat162(
                        __float2bfloat16(v0 - __bfloat162float(h0)),
                        __float2bfloat16(v1 - __bfloat162float(h1)));
                } else {  // OUT_SPLIT_T: [col][row]
                    bf16 h0 = __float2bfloat16(v0), h1 = __float2bfloat16(v1);
                    Ch[(size_t)col * M + row] = h0;
                    Ch[(size_t)(col + 1) * M + row] = h1;
                    Cm[(size_t)col * M + row] =
                        __float2bfloat16(v0 - __bfloat162float(h0));
                    Cm[(size_t)(col + 1) * M + row] =
                        __float2bfloat16(v1 - __bfloat162float(h1));
                }
            }
        }
    }
}

// ---------------- prep / split kernels ----------------
__global__ void prep_kernel(const int* __restrict__ dialog_state,
                            const int* __restrict__ sym_mask,
                            bf16* __restrict__ state_bf,
                            bf16* __restrict__ symmask_bf) {
    int i = blockIdx.x * blockDim.x + threadIdx.x;
    if (i < Bdim * DST) {
        int v = dialog_state[i];
        state_bf[i] = __float2bfloat16((v == 1) ? 1.0f : ((v == -1) ? -1.0f : 0.0f));
    }
    if (i < Bdim * SYM) symmask_bf[i] = __float2bfloat16((float)sym_mask[i]);
}

// transpose + split: in [K][N] fp32 -> hiT/midT [N][K] bf16. K,N % 32 == 0.
__global__ void splitT_kernel(const float* __restrict__ in,
                              bf16* __restrict__ hiT, bf16* __restrict__ midT,
                              int K, int N) {
    __shared__ float t[32][33];
    int tx = threadIdx.x, ty = threadIdx.y;
    int n0 = blockIdx.x * 32, k0 = blockIdx.y * 32;
#pragma unroll
    for (int j = ty; j < 32; j += 8)
        t[j][tx] = in[(size_t)(k0 + j) * N + n0 + tx];
    __syncthreads();
#pragma unroll
    for (int j = ty; j < 32; j += 8) {
        float v = t[tx][j];
        bf16 h = __float2bfloat16(v);
        size_t o = (size_t)(n0 + j) * K + k0 + tx;
        hiT[o] = h;
        midT[o] = __float2bfloat16(v - __bfloat162float(h));
    }
}

__global__ void softmax_mask_kernel(const float* __restrict__ logits,
                                    const int* __restrict__ dmask,
                                    float* __restrict__ out,
                                    bf16* __restrict__ oh, bf16* __restrict__ om) {
    int gw = (blockIdx.x * blockDim.x + threadIdx.x) >> 5;
    int lane = threadIdx.x & 31;
    if (gw >= Bdim) return;
    const float* row = logits + (size_t)gw * DIS;
    float v0 = row[lane], v1 = row[lane + 32], v2 = row[lane + 64], v3 = row[lane + 96];
    float mx = fmaxf(fmaxf(v0, v1), fmaxf(v2, v3));
#pragma unroll
    for (int o = 16; o; o >>= 1) mx = fmaxf(mx, __shfl_xor_sync(0xffffffffu, mx, o));
    v0 = expf(v0 - mx); v1 = expf(v1 - mx); v2 = expf(v2 - mx); v3 = expf(v3 - mx);
    float s = v0 + v1 + v2 + v3;
#pragma unroll
    for (int o = 16; o; o >>= 1) s += __shfl_xor_sync(0xffffffffu, s, o);
    float inv = 1.0f / s;
    const int* dm = dmask + (size_t)gw * DIS;
    size_t base = (size_t)gw * DIS;
#pragma unroll
    for (int q = 0; q < 4; q++) {
        float v = (q == 0 ? v0 : q == 1 ? v1 : q == 2 ? v2 : v3) * inv *
                  (float)dm[lane + q * 32];
        size_t o = base + lane + q * 32;
        out[o] = v;
        bf16 h = __float2bfloat16(v);
        oh[o] = h;
        om[o] = __float2bfloat16(v - __bfloat162float(h));
    }
}

__global__ void mu_kernel(const float* __restrict__ hm,
                          const float* __restrict__ Wm2,
                          const float* __restrict__ bm2,
                          float* __restrict__ mu) {
    int gw = (blockIdx.x * blockDim.x + threadIdx.x) >> 5;
    int lane = threadIdx.x & 31;
    if (gw >= Bdim) return;
    const float* row = hm + (size_t)gw * HIDD;
    float s = 0.0f;
#pragma unroll
    for (int j = 0; j < HIDD / 32; j++)
        s = fmaf(row[lane + 32 * j], Wm2[lane + 32 * j], s);
#pragma unroll
    for (int o = 16; o; o >>= 1) s += __shfl_xor_sync(0xffffffffu, s, o);
    if (lane == 0) mu[gw] = 1.0f / (1.0f + expf(-(s + bm2[0])));
}

// ---------------- launch ----------------
#define SMEM_MT4 (2 * (2 * 128 * 80 + 2 * BTILE_B))   // 81920
#define SMEM_MT2 (2 * (2 * 64 * 80 + 2 * BTILE_B))    // 61440

extern "C" void kernel_launch(void* const* d_in, const int* in_sizes, int n_in,
                              void* d_out, int out_size) {
    const int*   dialog_state  = (const int*)d_in[0];
    const float* dsr           = (const float*)d_in[1];
    const float* kg_adj        = (const float*)d_in[2];
    const int*   sym_flag      = (const int*)d_in[3];
    const int*   sym_mask      = (const int*)d_in[4];
    const int*   disease_mask  = (const int*)d_in[5];
    const int*   symptoms_mask = (const int*)d_in[6];
    const float* W_g  = (const float*)d_in[7];
    const float* Wd1  = (const float*)d_in[8];
    const float* bd1  = (const float*)d_in[9];
    const float* W1   = (const float*)d_in[10];
    const float* b1   = (const float*)d_in[11];
    const float* W2   = (const float*)d_in[12];
    const float* b2   = (const float*)d_in[13];
    const float* Wm1  = (const float*)d_in[14];
    const float* bm1  = (const float*)d_in[15];
    const float* Wm2  = (const float*)d_in[16];
    const float* bm2  = (const float*)d_in[17];
    const float* m_d  = (const float*)d_in[18];

    float* out = (float*)d_out;
    float* disease_out = out;
    float* symptom_out = out + (size_t)Bdim * DIS;

    bf16* bp = nullptr;  float* fp = nullptr;
    cudaGetSymbolAddress((void**)&bp, g_bf);
    cudaGetSymbolAddress((void**)&fp, g_f32);

    float* hm      = fp + F_HM;
    float* symtf   = fp + F_SYMTF;
    float* mu      = fp + F_MU;
    float* dlogits = fp + F_DLOG;

    cudaFuncSetAttribute(mgemm<ACT_RELU, A_F32, OUT_SPLIT_T, 2>, cudaFuncAttributeMaxDynamicSharedMemorySize, SMEM_MT2);
    cudaFuncSetAttribute(mgemm<ACT_NONE, A_F32, OUT_SPLIT, 4>,   cudaFuncAttributeMaxDynamicSharedMemorySize, SMEM_MT4);
    cudaFuncSetAttribute(mgemm<ACT_NONE, A_EXACT, OUT_F32, 4>,   cudaFuncAttributeMaxDynamicSharedMemorySize, SMEM_MT4);
    cudaFuncSetAttribute(mgemm<ACT_FSIG, A_PRE, OUT_F32, 4>,     cudaFuncAttributeMaxDynamicSharedMemorySize, SMEM_MT4);
    cudaFuncSetAttribute(mgemm<ACT_RELU, A_PRE, OUT_SPLIT, 4>,   cudaFuncAttributeMaxDynamicSharedMemorySize, SMEM_MT4);
    cudaFuncSetAttribute(mgemm<ACT_RELU, A_EXACT, OUT_F32, 4>,   cudaFuncAttributeMaxDynamicSharedMemorySize, SMEM_MT4);
    cudaFuncSetAttribute(mgemm<ACT_FINAL, A_PRE, OUT_F32, 4>,    cudaFuncAttributeMaxDynamicSharedMemorySize, SMEM_MT4);

    prep_kernel<<<(Bdim * DST + 255) / 256, 256>>>(dialog_state, sym_mask,
                                                   bp + O_STU, bp + O_SYMM);
    dim3 tb(32, 8);
    splitT_kernel<<<dim3(DEMB / 32, Edim / 32), tb>>>(W_g, bp + O_WG_H, bp + O_WG_M, Edim, DEMB);
    splitT_kernel<<<dim3(DIS / 32, SYM / 32), tb>>>(Wd1, bp + O_WD1_H, bp + O_WD1_M, SYM, DIS);
    splitT_kernel<<<dim3(HIDD / 32, DEMB / 32), tb>>>(W1, bp + O_W1_H, bp + O_W1_M, DEMB, HIDD);
    splitT_kernel<<<dim3(SYM / 32, HIDD / 32), tb>>>(W2, bp + O_W2_H, bp + O_W2_M, HIDD, SYM);
    splitT_kernel<<<dim3(HIDD / 32, DST / 32), tb>>>(Wm1, bp + O_WM1_H, bp + O_WM1_M, DST, HIDD);
    splitT_kernel<<<dim3(SYM / 32, DIS / 32), tb>>>(m_d, bp + O_MD_H, bp + O_MD_M, DIS, SYM);

    // G1: graph_rep^T = relu(kg_adj @ W_g)^T -> split T  [DEMB][E]; A fp32 fused
    mgemm<ACT_RELU, A_F32, OUT_SPLIT_T, 2><<<dim3(DEMB / 128, Edim / 64), 256, SMEM_MT2>>>(
        nullptr, nullptr, kg_adj, bp + O_WG_H, bp + O_WG_M,
        nullptr, nullptr, bp + O_GR_H, bp + O_GR_M,
        Edim, DEMB, Edim, nullptr, nullptr, nullptr, nullptr);

    // G2: state = dsr @ graph_rep -> split  [B][DEMB], K=E; A fp32 fused
    mgemm<ACT_NONE, A_F32, OUT_SPLIT, 4><<<dim3(DEMB / 128, Bdim / 128), 256, SMEM_MT4>>>(
        nullptr, nullptr, dsr, bp + O_GR_H, bp + O_GR_M,
        nullptr, nullptr, bp + O_ST_H, bp + O_ST_M,
        Bdim, DEMB, Edim, nullptr, nullptr, nullptr, nullptr);

    // G3: dlogits = sym_mask @ Wd1 + bd1 (A exact)  [B][DIS], K=SYM
    mgemm<ACT_NONE, A_EXACT, OUT_F32, 4><<<dim3(DIS / 128, Bdim / 128), 256, SMEM_MT4>>>(
        bp + O_SYMM, nullptr, nullptr, bp + O_WD1_H, bp + O_WD1_M,
        bd1, dlogits, nullptr, nullptr,
        Bdim, DIS, SYM, nullptr, nullptr, nullptr, nullptr);

    softmax_mask_kernel<<<Bdim / 8, 256>>>(dlogits, disease_mask, disease_out,
                                           bp + O_DIS_H, bp + O_DIS_M);

    // G4: symtf = filter_sig(disease @ m_d)  [B][SYM], K=DIS
    mgemm<ACT_FSIG, A_PRE, OUT_F32, 4><<<dim3(SYM / 128, Bdim / 128), 256, SMEM_MT4>>>(
        bp + O_DIS_H, bp + O_DIS_M, nullptr, bp + O_MD_H, bp + O_MD_M,
        nullptr, symtf, nullptr, nullptr,
        Bdim, SYM, DIS, nullptr, nullptr, nullptr, nullptr);

    // G5: h1 = relu(state @ W1 + b1) -> split  [B][HID], K=DEMB
    mgemm<ACT_RELU, A_PRE, OUT_SPLIT, 4><<<dim3(HIDD / 128, Bdim / 128), 256, SMEM_MT4>>>(
        bp + O_ST_H, bp + O_ST_M, nullptr, bp + O_W1_H, bp + O_W1_M,
        b1, nullptr, bp + O_H1_H, bp + O_H1_M,
        Bdim, HIDD, DEMB, nullptr, nullptr, nullptr, nullptr);

    // G6: hm = relu(state_ @ Wm1 + bm1) (A exact)  [B][HID], K=DST
    mgemm<ACT_RELU, A_EXACT, OUT_F32, 4><<<dim3(HIDD / 128, Bdim / 128), 256, SMEM_MT4>>>(
        bp + O_STU, nullptr, nullptr, bp + O_WM1_H, bp + O_WM1_M,
        bm1, hm, nullptr, nullptr,
        Bdim, HIDD, DST, nullptr, nullptr, nullptr, nullptr);

    mu_kernel<<<Bdim / 8, 256>>>(hm, Wm2, bm2, mu);

    // G7: symptom_final  [B][SYM], K=HID
    mgemm<ACT_FINAL, A_PRE, OUT_F32, 4><<<dim3(SYM / 128, Bdim / 128), 256, SMEM_MT4>>>(
        bp + O_H1_H, bp + O_H1_M, nullptr, bp + O_W2_H, bp + O_W2_M,
        b2, symptom_out, nullptr, nullptr,
        Bdim, SYM, HIDD, mu, symtf, sym_flag, symptoms_mask);
}

// round 9
// speedup vs baseline: 2.8344x; 1.0223x over previous
#include <cuda_runtime.h>
#include <cuda_bf16.h>
#include <math.h>
#include <stdint.h>

#define Bdim 8192
#define Edim 4096
#define DEMB 256
#define HIDD 1024
#define DIS 128
#define SYM 512
#define DST 640   // DIS + SYM

enum { ACT_NONE = 0, ACT_RELU = 1, ACT_FSIG = 2, ACT_FINAL = 3 };
enum { OUT_F32 = 0, OUT_SPLIT = 1, OUT_SPLIT_T = 2 };
enum { A_PRE = 0, A_EXACT = 1, A_F32 = 2 };

typedef __nv_bfloat16 bf16;

// ---------------- scratch layout ----------------
constexpr size_t N_ST   = (size_t)Bdim * DEMB;
constexpr size_t N_H1   = (size_t)Bdim * HIDD;
constexpr size_t N_DIS  = (size_t)Bdim * DIS;
constexpr size_t N_SYMM = (size_t)Bdim * SYM;
constexpr size_t N_STU  = (size_t)Bdim * DST;
constexpr size_t N_WG   = (size_t)Edim * DEMB;
constexpr size_t N_GR   = (size_t)Edim * DEMB;
constexpr size_t N_WD1  = (size_t)SYM * DIS;
constexpr size_t N_W1   = (size_t)DEMB * HIDD;
constexpr size_t N_W2   = (size_t)HIDD * SYM;
constexpr size_t N_WM1  = (size_t)DST * HIDD;
constexpr size_t N_MD   = (size_t)DIS * SYM;

constexpr size_t O_ST_H  = 0;
constexpr size_t O_ST_M  = O_ST_H  + N_ST;
constexpr size_t O_H1_H  = O_ST_M  + N_ST;
constexpr size_t O_H1_M  = O_H1_H  + N_H1;
constexpr size_t O_DIS_H = O_H1_M  + N_H1;
constexpr size_t O_DIS_M = O_DIS_H + N_DIS;
constexpr size_t O_SYMM  = O_DIS_M + N_DIS;
constexpr size_t O_STU   = O_SYMM  + N_SYMM;
constexpr size_t O_WG_H  = O_STU   + N_STU;   // W_g^T   [DEMB][E]
constexpr size_t O_WG_M  = O_WG_H  + N_WG;
constexpr size_t O_GR_H  = O_WG_M  + N_WG;    // graph_rep^T [DEMB][E]
constexpr size_t O_GR_M  = O_GR_H  + N_GR;
constexpr size_t O_WD1_H = O_GR_M  + N_GR;    // Wd1^T [DIS][SYM]
constexpr size_t O_WD1_M = O_WD1_H + N_WD1;
constexpr size_t O_W1_H  = O_WD1_M + N_WD1;   // W1^T  [HID][DEMB]
constexpr size_t O_W1_M  = O_W1_H  + N_W1;
constexpr size_t O_W2_H  = O_W1_M  + N_W1;    // W2^T  [SYM][HID]
constexpr size_t O_W2_M  = O_W2_H  + N_W2;
constexpr size_t O_WM1_H = O_W2_M  + N_W2;    // Wm1^T [HID][DST]
constexpr size_t O_WM1_M = O_WM1_H + N_WM1;
constexpr size_t O_MD_H  = O_WM1_M + N_WM1;   // m_d^T [SYM][DIS]
constexpr size_t O_MD_M  = O_MD_H  + N_MD;
constexpr size_t BF_TOTAL = O_MD_M + N_MD;

constexpr size_t F_HM    = 0;
constexpr size_t F_SYMTF = F_HM + (size_t)Bdim * HIDD;
constexpr size_t F_MU    = F_SYMTF + (size_t)Bdim * SYM;
constexpr size_t F_DLOG  = F_MU + Bdim;
constexpr size_t F_TOTAL = F_DLOG + (size_t)Bdim * DIS;

__device__ __align__(16) bf16  g_bf[BF_TOTAL];
__device__ __align__(16) float g_f32[F_TOTAL];

// ---------------- PTX helpers (sm_80-era only) ----------------
__device__ __forceinline__ uint32_t smem_u32(const void* p) {
    uint32_t a;
    asm("{ .reg .u64 t; cvta.to.shared.u64 t, %1; cvt.u32.u64 %0, t; }"
        : "=r"(a) : "l"(p));
    return a;
}
__device__ __forceinline__ void cpasync16(uint32_t dst, const void* src) {
    asm volatile("cp.async.cg.shared.global [%0], [%1], 16;" :: "r"(dst), "l"(src));
}
__device__ __forceinline__ void ldmat_x4(uint32_t* r, uint32_t addr) {
    asm volatile("ldmatrix.sync.aligned.m8n8.x4.shared.b16 {%0,%1,%2,%3}, [%4];"
                 : "=r"(r[0]), "=r"(r[1]), "=r"(r[2]), "=r"(r[3]) : "r"(addr));
}
__device__ __forceinline__ void mma16816(float* d, const uint32_t* a,
                                         uint32_t b0, uint32_t b1) {
    asm volatile("mma.sync.aligned.m16n8k16.row.col.f32.bf16.bf16.f32 "
                 "{%0,%1,%2,%3}, {%4,%5,%6,%7}, {%8,%9}, {%0,%1,%2,%3};"
                 : "+f"(d[0]), "+f"(d[1]), "+f"(d[2]), "+f"(d[3])
                 : "r"(a[0]), "r"(a[1]), "r"(a[2]), "r"(a[3]), "r"(b0), "r"(b1));
}

// ---------------- mma.sync GEMM ----------------
// C[M,N] = act(A @ B + bias); A[M][K], B as BT[N][K], bf16 hi/mid split.
// BM = 32*MT, BN = 128. BK=32. 256 thr, 8 warps (2M x 4N), warp tile (16*MT)x32.
#define BTILE_B 10240           // 128 rows * 80 B (64B data + 16B pad)

template <int ACT, int AMODE, int OMODE, int MT>
__global__ __launch_bounds__(256) void mgemm(
    const bf16* __restrict__ Ah, const bf16* __restrict__ Am,
    const float* __restrict__ Af,
    const bf16* __restrict__ BhT, const bf16* __restrict__ BmT,
    const float* __restrict__ bias, float* __restrict__ C,
    bf16* __restrict__ Ch, bf16* __restrict__ Cm,
    int M, int N, int K,
    const float* __restrict__ mu, const float* __restrict__ symtf,
    const int* __restrict__ sflag, const int* __restrict__ smask) {
    constexpr int BM = 32 * MT;
    constexpr int A_T = BM * 80;            // bytes per A half-tile in smem
    constexpr int STAGE = 2 * A_T + 2 * BTILE_B;
    constexpr int NV = BM / 32;             // float4 per thread for A_F32
    constexpr int AI = (BM * 4 + 255) / 256;// cp.async iters for A

    extern __shared__ __align__(128) char smem[];
    uint32_t sb = smem_u32(smem);
    int tid = threadIdx.x, wid = tid >> 5, lane = tid & 31;
    int bx = blockIdx.x, by = blockIdx.y;
    int wm = wid & 1, wn = wid >> 1;

    const bf16* pa_h = (AMODE == A_F32) ? nullptr : Ah + (size_t)by * BM * K;
    const bf16* pa_m = (AMODE == A_PRE) ? Am + (size_t)by * BM * K : pa_h;
    const float* paf = (AMODE == A_F32) ? Af + (size_t)by * BM * K : nullptr;
    const bf16* pb_h = BhT + (size_t)bx * 128 * K;
    const bf16* pb_m = BmT + (size_t)bx * 128 * K;
    int nc = K / 32;

    float acc[MT][4][4];
#pragma unroll
    for (int i = 0; i < MT; i++)
#pragma unroll
        for (int j = 0; j < 4; j++)
#pragma unroll
            for (int q = 0; q < 4; q++) acc[i][j][q] = 0.0f;

    // ---- helpers as lambdas ----
    auto copyB = [&](uint32_t base, int k0) {
#pragma unroll
        for (int h = 0; h < 2; h++) {
            int c = tid + h * 256;
            int row = c >> 2, seg = c & 3;
            uint32_t off = (uint32_t)row * 80u + (uint32_t)seg * 16u;
            size_t g = (size_t)row * K + k0 + seg * 8;
            cpasync16(base + 2 * A_T + off, pb_h + g);
            cpasync16(base + 2 * A_T + BTILE_B + off, pb_m + g);
        }
    };
    auto copyA_pre = [&](uint32_t base, int k0) {
#pragma unroll
        for (int h = 0; h < AI; h++) {
            int c = tid + h * 256;
            if (BM * 4 % 256 != 0 && c >= BM * 4) break;
            int row = c >> 2, seg = c & 3;
            uint32_t off = (uint32_t)row * 80u + (uint32_t)seg * 16u;
            size_t g = (size_t)row * K + k0 + seg * 8;
            cpasync16(base + off, pa_h + g);
            if (AMODE == A_PRE) cpasync16(base + A_T + off, pa_m + g);
        }
    };
    auto stsA_f32 = [&](char* cbase, const float4* v) {
#pragma unroll
        for (int i = 0; i < NV; i++) {
            int idx = tid + i * 256;
            int row = idx >> 3, c4 = idx & 7;
            char* d = cbase + row * 80 + c4 * 8;
            bf16 h0 = __float2bfloat16(v[i].x), h1 = __float2bfloat16(v[i].y);
            bf16 h2 = __float2bfloat16(v[i].z), h3 = __float2bfloat16(v[i].w);
            *(__nv_bfloat162*)(d)     = __halves2bfloat162(h0, h1);
            *(__nv_bfloat162*)(d + 4) = __halves2bfloat162(h2, h3);
            char* dm = d + A_T;
            *(__nv_bfloat162*)(dm)     = __halves2bfloat162(
                __float2bfloat16(v[i].x - __bfloat162float(h0)),
                __float2bfloat16(v[i].y - __bfloat162float(h1)));
            *(__nv_bfloat162*)(dm + 4) = __halves2bfloat162(
                __float2bfloat16(v[i].z - __bfloat162float(h2)),
                __float2bfloat16(v[i].w - __bfloat162float(h3)));
        }
    };
    auto ldgA_f32 = [&](float4* v, int k0) {
#pragma unroll
        for (int i = 0; i < NV; i++) {
            int idx = tid + i * 256;
            int row = idx >> 3, c4 = idx & 7;
            v[i] = *(const float4*)(paf + (size_t)row * K + k0 + c4 * 4);
        }
    };

    // ---- prologue: stage 0 ----
    if (AMODE == A_F32) {
        float4 v0[NV];
        ldgA_f32(v0, 0);
        stsA_f32(smem, v0);
    } else {
        copyA_pre(sb, 0);
    }
    copyB(sb, 0);
    asm volatile("cp.async.commit_group;" ::: "memory");
    asm volatile("cp.async.wait_group 0;" ::: "memory");
    __syncthreads();

    // ---- main loop ----
    for (int k = 0; k < nc; k++) {
        int st = k & 1;
        uint32_t sbase = sb + st * STAGE;
        char* cbase_n = smem + (st ^ 1) * STAGE;
        uint32_t sbase_n = sb + (st ^ 1) * STAGE;

        float4 afv[NV];
        bool more = (k + 1 < nc);
        if (more) {
            if (AMODE == A_F32) ldgA_f32(afv, (k + 1) * 32);
            else copyA_pre(sbase_n, (k + 1) * 32);
            copyB(sbase_n, (k + 1) * 32);
            asm volatile("cp.async.commit_group;" ::: "memory");
        }

        uint32_t sA_h = sbase;
        uint32_t sA_m = sbase + A_T;
        uint32_t sB_h = sbase + 2 * A_T;
        uint32_t sB_m = sbase + 2 * A_T + BTILE_B;
#pragma unroll
        for (int kk = 0; kk < 2; kk++) {
            uint32_t kb = kk * 32;
            uint32_t afr[MT][4], bfr[2][4];
            auto ldA = [&](uint32_t aB) {
#pragma unroll
                for (int mt = 0; mt < MT; mt++)
                    ldmat_x4(afr[mt],
                             aB + (uint32_t)(wm * (16 * MT) + mt * 16 + (lane & 15)) * 80
                                + kb + (uint32_t)(lane >> 4) * 16);
            };
            auto ldB = [&](uint32_t bB) {
#pragma unroll
                for (int pr = 0; pr < 2; pr++)
                    ldmat_x4(bfr[pr],
                             bB + (uint32_t)(wn * 32 + pr * 16 + (lane & 15)) * 80
                                + kb + (uint32_t)(lane >> 4) * 16);
            };
            auto domma = [&]() {
#pragma unroll
                for (int mt = 0; mt < MT; mt++)
#pragma unroll
                    for (int nt = 0; nt < 4; nt++)
                        mma16816(acc[mt][nt], afr[mt],
                                 bfr[nt >> 1][nt & 1], bfr[nt >> 1][(nt & 1) + 2]);
            };
            // fragment-reuse ordering: ah*bh, ah*bm (A frags reused), am*bh
            ldA(sA_h); ldB(sB_h); domma();
            ldB(sB_m); domma();
            if (AMODE != A_EXACT) {
                ldA(sA_m); ldB(sB_h); domma();
            }
        }

        if (more) {
            if (AMODE == A_F32) stsA_f32(cbase_n, afv);
            asm volatile("cp.async.wait_group 0;" ::: "memory");
        }
        __syncthreads();
    }

    // ---------------- epilogue ----------------
#pragma unroll
    for (int mt = 0; mt < MT; mt++) {
#pragma unroll
        for (int nt = 0; nt < 4; nt++) {
#pragma unroll
            for (int i2 = 0; i2 < 2; i2++) {
                int row = by * BM + wm * (16 * MT) + mt * 16 + (lane >> 2) + i2 * 8;
                int col = bx * 128 + wn * 32 + nt * 8 + (lane & 3) * 2;
                float v0 = acc[mt][nt][i2 * 2 + 0];
                float v1 = acc[mt][nt][i2 * 2 + 1];
                if (bias) { v0 += bias[col]; v1 += bias[col + 1]; }
                if (ACT == ACT_RELU) {
                    v0 = fmaxf(v0, 0.0f); v1 = fmaxf(v1, 0.0f);
                } else if (ACT == ACT_FSIG) {
                    v0 = (v0 > 0.0f) ? 1.0f / (1.0f + expf(-v0)) : v0;
                    v1 = (v1 > 0.0f) ? 1.0f / (1.0f + expf(-v1)) : v1;
                } else if (ACT == ACT_FINAL) {
                    float m = mu[row];
                    size_t o = (size_t)row * SYM + col;
                    float p0 = 1.0f / (1.0f + expf(-v0));
                    float p1 = 1.0f / (1.0f + expf(-v1));
                    v0 = (m * p0 + (1.0f - m) * symtf[o]) *
                         (float)sflag[o] * (float)smask[o];
                    v1 = (m * p1 + (1.0f - m) * symtf[o + 1]) *
                         (float)sflag[o + 1] * (float)smask[o + 1];
                }
                if (OMODE == OUT_F32) {
                    *(float2*)(C + (size_t)row * N + col) = make_float2(v0, v1);
                } else if (OMODE == OUT_SPLIT) {
                    bf16 h0 = __float2bfloat16(v0), h1 = __float2bfloat16(v1);
                    size_t o = (size_t)row * N + col;
                    *(__nv_bfloat162*)(Ch + o) = __halves2bfloat162(h0, h1);
                    *(__nv_bfloat162*)(Cm + o) = __halves2bfloat162(
                        __float2bfloat16(v0 - __bfloat162float(h0)),
                        __float2bfloat16(v1 - __bfloat162float(h1)));
                } else {  // OUT_SPLIT_T: [col][row]
                    bf16 h0 = __float2bfloat16(v0), h1 = __float2bfloat16(v1);
                    Ch[(size_t)col * M + row] = h0;
                    Ch[(size_t)(col + 1) * M + row] = h1;
                    Cm[(size_t)col * M + row] =
                        __float2bfloat16(v0 - __bfloat162float(h0));
                    Cm[(size_t)(col + 1) * M + row] =
                        __float2bfloat16(v1 - __bfloat162float(h1));
                }
            }
        }
    }
}

// ---------------- prep / split kernels ----------------
__global__ void prep_kernel(const int* __restrict__ dialog_state,
                            const int* __restrict__ sym_mask,
                            bf16* __restrict__ state_bf,
                            bf16* __restrict__ symmask_bf) {
    int i = blockIdx.x * blockDim.x + threadIdx.x;
    if (i < Bdim * DST) {
        int v = dialog_state[i];
        state_bf[i] = __float2bfloat16((v == 1) ? 1.0f : ((v == -1) ? -1.0f : 0.0f));
    }
    if (i < Bdim * SYM) symmask_bf[i] = __float2bfloat16((float)sym_mask[i]);
}

// transpose + split one 32x32 tile: in [K][N] fp32 -> hiT/midT [N][K] bf16.
__device__ __forceinline__ void splitT_tile(const float* __restrict__ in,
                                            bf16* __restrict__ hiT,
                                            bf16* __restrict__ midT,
                                            int K, int N, int n0, int k0,
                                            float (*t)[33]) {
    int tx = threadIdx.x, ty = threadIdx.y;
#pragma unroll
    for (int j = ty; j < 32; j += 8)
        t[j][tx] = in[(size_t)(k0 + j) * N + n0 + tx];
    __syncthreads();
#pragma unroll
    for (int j = ty; j < 32; j += 8) {
        float v = t[tx][j];
        bf16 h = __float2bfloat16(v);
        size_t o = (size_t)(n0 + j) * K + k0 + tx;
        hiT[o] = h;
        midT[o] = __float2bfloat16(v - __bfloat162float(h));
    }
}

__global__ void splitT_kernel(const float* __restrict__ in,
                              bf16* __restrict__ hiT, bf16* __restrict__ midT,
                              int K, int N) {
    __shared__ float t[32][33];
    splitT_tile(in, hiT, midT, K, N, blockIdx.x * 32, blockIdx.y * 32, t);
}

// batched split for the 5 remaining weights (one launch)
__global__ void splitT_batch(const float* __restrict__ Wd1,
                             const float* __restrict__ W1,
                             const float* __restrict__ W2,
                             const float* __restrict__ Wm1,
                             const float* __restrict__ m_d,
                             bf16* __restrict__ bp) {
    __shared__ float t[32][33];
    int b = blockIdx.x;
    const float* in; bf16 *hiT, *midT; int K, N, tile;
    if (b < 64)        { in = Wd1; hiT = bp + O_WD1_H; midT = bp + O_WD1_M; K = SYM;  N = DIS;  tile = b; }
    else if (b < 320)  { in = W1;  hiT = bp + O_W1_H;  midT = bp + O_W1_M;  K = DEMB; N = HIDD; tile = b - 64; }
    else if (b < 832)  { in = W2;  hiT = bp + O_W2_H;  midT = bp + O_W2_M;  K = HIDD; N = SYM;  tile = b - 320; }
    else if (b < 1472) { in = Wm1; hiT = bp + O_WM1_H; midT = bp + O_WM1_M; K = DST;  N = HIDD; tile = b - 832; }
    else               { in = m_d; hiT = bp + O_MD_H;  midT = bp + O_MD_M;  K = DIS;  N = SYM;  tile = b - 1472; }
    int ntx = N / 32;
    splitT_tile(in, hiT, midT, K, N, (tile % ntx) * 32, (tile / ntx) * 32, t);
}

__global__ void softmax_mask_kernel(const float* __restrict__ logits,
                                    const int* __restrict__ dmask,
                                    float* __restrict__ out,
                                    bf16* __restrict__ oh, bf16* __restrict__ om) {
    int gw = (blockIdx.x * blockDim.x + threadIdx.x) >> 5;
    int lane = threadIdx.x & 31;
    if (gw >= Bdim) return;
    const float* row = logits + (size_t)gw * DIS;
    float v0 = row[lane], v1 = row[lane + 32], v2 = row[lane + 64], v3 = row[lane + 96];
    float mx = fmaxf(fmaxf(v0, v1), fmaxf(v2, v3));
#pragma unroll
    for (int o = 16; o; o >>= 1) mx = fmaxf(mx, __shfl_xor_sync(0xffffffffu, mx, o));
    v0 = expf(v0 - mx); v1 = expf(v1 - mx); v2 = expf(v2 - mx); v3 = expf(v3 - mx);
    float s = v0 + v1 + v2 + v3;
#pragma unroll
    for (int o = 16; o; o >>= 1) s += __shfl_xor_sync(0xffffffffu, s, o);
    float inv = 1.0f / s;
    const int* dm = dmask + (size_t)gw * DIS;
    size_t base = (size_t)gw * DIS;
#pragma unroll
    for (int q = 0; q < 4; q++) {
        float v = (q == 0 ? v0 : q == 1 ? v1 : q == 2 ? v2 : v3) * inv *
                  (float)dm[lane + q * 32];
        size_t o = base + lane + q * 32;
        out[o] = v;
        bf16 h = __float2bfloat16(v);
        oh[o] = h;
        om[o] = __float2bfloat16(v - __bfloat162float(h));
    }
}

__global__ void mu_kernel(const float* __restrict__ hm,
                          const float* __restrict__ Wm2,
                          const float* __restrict__ bm2,
                          float* __restrict__ mu) {
    int gw = (blockIdx.x * blockDim.x + threadIdx.x) >> 5;
    int lane = threadIdx.x & 31;
    if (gw >= Bdim) return;
    const float* row = hm + (size_t)gw * HIDD;
    float s = 0.0f;
#pragma unroll
    for (int j = 0; j < HIDD / 32; j++)
        s = fmaf(row[lane + 32 * j], Wm2[lane + 32 * j], s);
#pragma unroll
    for (int o = 16; o; o >>= 1) s += __shfl_xor_sync(0xffffffffu, s, o);
    if (lane == 0) mu[gw] = 1.0f / (1.0f + expf(-(s + bm2[0])));
}

// ---------------- launch ----------------
#define SMEM_MT4 (2 * (2 * 128 * 80 + 2 * BTILE_B))   // 81920
#define SMEM_MT2 (2 * (2 * 64 * 80 + 2 * BTILE_B))    // 61440

extern "C" void kernel_launch(void* const* d_in, const int* in_sizes, int n_in,
                              void* d_out, int out_size) {
    const int*   dialog_state  = (const int*)d_in[0];
    const float* dsr           = (const float*)d_in[1];
    const float* kg_adj        = (const float*)d_in[2];
    const int*   sym_flag      = (const int*)d_in[3];
    const int*   sym_mask      = (const int*)d_in[4];
    const int*   disease_mask  = (const int*)d_in[5];
    const int*   symptoms_mask = (const int*)d_in[6];
    const float* W_g  = (const float*)d_in[7];
    const float* Wd1  = (const float*)d_in[8];
    const float* bd1  = (const float*)d_in[9];
    const float* W1   = (const float*)d_in[10];
    const float* b1   = (const float*)d_in[11];
    const float* W2   = (const float*)d_in[12];
    const float* b2   = (const float*)d_in[13];
    const float* Wm1  = (const float*)d_in[14];
    const float* bm1  = (const float*)d_in[15];
    const float* Wm2  = (const float*)d_in[16];
    const float* bm2  = (const float*)d_in[17];
    const float* m_d  = (const float*)d_in[18];

    float* out = (float*)d_out;
    float* disease_out = out;
    float* symptom_out = out + (size_t)Bdim * DIS;

    bf16* bp = nullptr;  float* fp = nullptr;
    cudaGetSymbolAddress((void**)&bp, g_bf);
    cudaGetSymbolAddress((void**)&fp, g_f32);

    float* hm      = fp + F_HM;
    float* symtf   = fp + F_SYMTF;
    float* mu      = fp + F_MU;
    float* dlogits = fp + F_DLOG;

    cudaFuncSetAttribute(mgemm<ACT_RELU, A_F32, OUT_SPLIT_T, 2>, cudaFuncAttributeMaxDynamicSharedMemorySize, SMEM_MT2);
    cudaFuncSetAttribute(mgemm<ACT_NONE, A_F32, OUT_SPLIT, 4>,   cudaFuncAttributeMaxDynamicSharedMemorySize, SMEM_MT4);
    cudaFuncSetAttribute(mgemm<ACT_NONE, A_EXACT, OUT_F32, 4>,   cudaFuncAttributeMaxDynamicSharedMemorySize, SMEM_MT4);
    cudaFuncSetAttribute(mgemm<ACT_FSIG, A_PRE, OUT_F32, 4>,     cudaFuncAttributeMaxDynamicSharedMemorySize, SMEM_MT4);
    cudaFuncSetAttribute(mgemm<ACT_RELU, A_PRE, OUT_SPLIT, 4>,   cudaFuncAttributeMaxDynamicSharedMemorySize, SMEM_MT4);
    cudaFuncSetAttribute(mgemm<ACT_RELU, A_EXACT, OUT_F32, 4>,   cudaFuncAttributeMaxDynamicSharedMemorySize, SMEM_MT4);
    cudaFuncSetAttribute(mgemm<ACT_FINAL, A_PRE, OUT_F32, 4>,    cudaFuncAttributeMaxDynamicSharedMemorySize, SMEM_MT4);

    // Launch order arranged so ncu (-s 5 -c 1) profiles launch #6 = G2.
    // 1: prep
    prep_kernel<<<(Bdim * DST + 255) / 256, 256>>>(dialog_state, sym_mask,
                                                   bp + O_STU, bp + O_SYMM);
    // 2: split W_g
    dim3 tb(32, 8);
    splitT_kernel<<<dim3(DEMB / 32, Edim / 32), tb>>>(W_g, bp + O_WG_H, bp + O_WG_M, Edim, DEMB);

    // 3: G1: graph_rep^T = relu(kg_adj @ W_g)^T -> split T  [DEMB][E]; A fp32 fused
    mgemm<ACT_RELU, A_F32, OUT_SPLIT_T, 2><<<dim3(DEMB / 128, Edim / 64), 256, SMEM_MT2>>>(
        nullptr, nullptr, kg_adj, bp + O_WG_H, bp + O_WG_M,
        nullptr, nullptr, bp + O_GR_H, bp + O_GR_M,
        Edim, DEMB, Edim, nullptr, nullptr, nullptr, nullptr);

    // 4: split remaining weights (batched, one launch)
    splitT_batch<<<1536, tb>>>(Wd1, W1, W2, Wm1, m_d, bp);

    // 5: G3: dlogits = sym_mask @ Wd1 + bd1 (A exact)  [B][DIS], K=SYM
    mgemm<ACT_NONE, A_EXACT, OUT_F32, 4><<<dim3(DIS / 128, Bdim / 128), 256, SMEM_MT4>>>(
        bp + O_SYMM, nullptr, nullptr, bp + O_WD1_H, bp + O_WD1_M,
        bd1, dlogits, nullptr, nullptr,
        Bdim, DIS, SYM, nullptr, nullptr, nullptr, nullptr);

    // 6: G2: state = dsr @ graph_rep -> split  [B][DEMB], K=E; A fp32 fused
    mgemm<ACT_NONE, A_F32, OUT_SPLIT, 4><<<dim3(DEMB / 128, Bdim / 128), 256, SMEM_MT4>>>(
        nullptr, nullptr, dsr, bp + O_GR_H, bp + O_GR_M,
        nullptr, nullptr, bp + O_ST_H, bp + O_ST_M,
        Bdim, DEMB, Edim, nullptr, nullptr, nullptr, nullptr);

    // 7: softmax
    softmax_mask_kernel<<<Bdim / 8, 256>>>(dlogits, disease_mask, disease_out,
                                           bp + O_DIS_H, bp + O_DIS_M);

    // 8: G4: symtf = filter_sig(disease @ m_d)  [B][SYM], K=DIS
    mgemm<ACT_FSIG, A_PRE, OUT_F32, 4><<<dim3(SYM / 128, Bdim / 128), 256, SMEM_MT4>>>(
        bp + O_DIS_H, bp + O_DIS_M, nullptr, bp + O_MD_H, bp + O_MD_M,
        nullptr, symtf, nullptr, nullptr,
        Bdim, SYM, DIS, nullptr, nullptr, nullptr, nullptr);

    // 9: G5: h1 = relu(state @ W1 + b1) -> split  [B][HID], K=DEMB
    mgemm<ACT_RELU, A_PRE, OUT_SPLIT, 4><<<dim3(HIDD / 128, Bdim / 128), 256, SMEM_MT4>>>(
        bp + O_ST_H, bp + O_ST_M, nullptr, bp + O_W1_H, bp + O_W1_M,
        b1, nullptr, bp + O_H1_H, bp + O_H1_M,
        Bdim, HIDD, DEMB, nullptr, nullptr, nullptr, nullptr);

    // 10: G6: hm = relu(state_ @ Wm1 + bm1) (A exact)  [B][HID], K=DST
    mgemm<ACT_RELU, A_EXACT, OUT_F32, 4><<<dim3(HIDD / 128, Bdim / 128), 256, SMEM_MT4>>>(
        bp + O_STU, nullptr, nullptr, bp + O_WM1_H, bp + O_WM1_M,
        bm1, hm, nullptr, nullptr,
        Bdim, HIDD, DST, nullptr, nullptr, nullptr, nullptr);

    // 11: mu
    mu_kernel<<<Bdim / 8, 256>>>(hm, Wm2, bm2, mu);

    // 12: G7: symptom_final  [B][SYM], K=HID
    mgemm<ACT_FINAL, A_PRE, OUT_F32, 4><<<dim3(SYM / 128, Bdim / 128), 256, SMEM_MT4>>>(
        bp + O_H1_H, bp + O_H1_M, nullptr, bp + O_W2_H, bp + O_W2_M,
        b2, symptom_out, nullptr, nullptr,
        Bdim, SYM, HIDD, mu, symtf, sym_flag, symptoms_mask);
}